// round 7
// baseline (speedup 1.0000x reference)
#include <cuda_runtime.h>
#include <cstdint>

// Problem constants
#define Bn    8
#define Tn    32
#define DIN   768
#define DSAE  8192
#define TOPK  64
#define MROWS 256
#define XHAT_ELEMS (MROWS * DIN)
#define Z_ELEMS    ((size_t)MROWS * DSAE)
#define WCAP  48

// GEMM tiling
#define MTW   64
#define NTW   64
#define KB    32
#define STAGES 3
#define A_STR 36
#define B_STR 72
#define A_F   (MTW * A_STR)
#define B_F   (KB * B_STR)
#define STAGE_F (A_F + B_F)
#define A_BYTES (A_F * 4)
#define STAGE_BYTES (STAGE_F * 4)

// ---------------- scratch (no allocations allowed) ----------------
__device__ float g_pre[(size_t)MROWS * DSAE];   // t-major rows: row = t*8+b
__device__ int   g_idx[MROWS * TOPK];
__device__ float g_val[MROWS * TOPK];
__device__ int   g_cnt[MROWS];
__device__ unsigned long long g_loss_acc;
__device__ int   g_done_ctr;

// ================= helpers (plain sm_80+ PTX only) =================
__device__ __forceinline__ uint32_t smem_u32(const void* p) {
    uint32_t a;
    asm("{ .reg .u64 t; cvta.to.shared.u64 t, %1; cvt.u32.u64 %0, t; }" : "=r"(a) : "l"(p));
    return a;
}
__device__ __forceinline__ void cp16(uint32_t dst, const void* src, int srcsize) {
    asm volatile("cp.async.cg.shared.global [%0], [%1], 16, %2;"
                 :: "r"(dst), "l"(src), "r"(srcsize) : "memory");
}
#define CP_COMMIT() asm volatile("cp.async.commit_group;" ::: "memory")
#define CP_WAIT1()  asm volatile("cp.async.wait_group 1;" ::: "memory")

__device__ __forceinline__ uint32_t tf32_of(float v) {
    uint32_t h;
    asm("cvt.rna.tf32.f32 %0, %1;" : "=r"(h) : "f"(v));
    return h;
}

__device__ __forceinline__ void mma8(float* c, const uint32_t* a, const uint32_t* b) {
    asm volatile(
        "mma.sync.aligned.m16n8k8.row.col.f32.tf32.tf32.f32 "
        "{%0,%1,%2,%3}, {%4,%5,%6,%7}, {%8,%9}, {%0,%1,%2,%3};"
        : "+f"(c[0]), "+f"(c[1]), "+f"(c[2]), "+f"(c[3])
        : "r"(a[0]), "r"(a[1]), "r"(a[2]), "r"(a[3]), "r"(b[0]), "r"(b[1]));
}

// =====================================================================
// Stage copy: A 64m x 32k causal im2col (cp.async zero-fill); B 32k x 64n.
// =====================================================================
__device__ __forceinline__ void copy_stage(
    uint32_t sbase, int kb, int m0,
    const float* __restrict__ x, const float* __restrict__ W, int s0, int tid)
{
#pragma unroll
    for (int q = 0; q < 4; ++q) {
        const int ch  = tid + q * 128;
        const int row = ch >> 3, c4 = ch & 7;
        const int kg  = kb * KB + c4 * 4;
        const int off = kg / DIN;
        const int d   = kg - off * DIN;
        const int mrow = m0 + row;
        const int t = mrow >> 3, b = mrow & 7;
        const bool ok = (off <= t);
        const int  tt = ok ? (t - off) : 0;
        const float* src = x + ((b * Tn + tt) * DIN + d);
        cp16(sbase + row * (A_STR * 4) + c4 * 16, src, ok ? 16 : 0);
    }
#pragma unroll
    for (int q = 0; q < 4; ++q) {
        const int ch = tid + q * 128;
        const int kr = ch >> 4, c = ch & 15;
        const float* src = W + (size_t)(kb * KB + kr) * DSAE + s0 + c * 4;
        cp16(sbase + A_BYTES + kr * (B_STR * 4) + c * 16, src, 16);
    }
}

// =====================================================================
// Dummy kernel: shifts ncu's -s 5 window so enc_mma lands on launch #6.
// =====================================================================
__global__ void dummy_kernel() {}

// =====================================================================
// Kernel 1: encoder GEMM, single-pass tf32 mma.sync.
// Grid (4, 128). Block 64m x 64n, 128 threads, warp tile 32x32.
// 3-stage cp.async pipeline -> 55.3KB smem -> 4 CTAs/SM (4 warps/SMSP).
// =====================================================================
__global__ __launch_bounds__(128, 4) void enc_mma_kernel(
    const float* __restrict__ x,
    const float* __restrict__ W,
    const float* __restrict__ b_enc)
{
    extern __shared__ float sm[];
    const uint32_t smb = smem_u32(sm);
    const int tid = threadIdx.x, lane = tid & 31, wid = tid >> 5;
    const int g   = blockIdx.x;
    const int s0  = blockIdx.y * NTW;
    const int m0  = g * MTW;
    const int nkb = 192 * (g + 1);
    const int wm  = (wid & 1) * 32, wn = (wid >> 1) * 32;

    if (blockIdx.x == 0 && blockIdx.y == 0 && tid == 0) {
        g_loss_acc = 0ULL;          // reset fused-loss accumulators (pre-decode)
        g_done_ctr = 0;
    }

    float acc[2][4][4];
#pragma unroll
    for (int a = 0; a < 2; ++a)
#pragma unroll
        for (int b = 0; b < 4; ++b)
#pragma unroll
            for (int c = 0; c < 4; ++c) acc[a][b][c] = 0.f;

#pragma unroll
    for (int p = 0; p < STAGES - 1; ++p) {
        copy_stage(smb + p * STAGE_BYTES, p, m0, x, W, s0, tid);
        CP_COMMIT();
    }

    const int rA = lane >> 2;
    const int cA = lane & 3;

    for (int i = 0; i < nkb; ++i) {
        CP_WAIT1();
        __syncthreads();   // stage i ready; all warps done with stage (i-1)

        const int nx = i + STAGES - 1;
        if (nx < nkb)
            copy_stage(smb + (nx % STAGES) * STAGE_BYTES, nx, m0, x, W, s0, tid);
        CP_COMMIT();

        const float* As = sm + (i % STAGES) * STAGE_F;
        const float* Bs = As + A_F;

#pragma unroll
        for (int ks = 0; ks < 4; ++ks) {
            uint32_t ah[2][4];
#pragma unroll
            for (int mt = 0; mt < 2; ++mt) {
                const int r = wm + mt * 16 + rA;
                const int c = ks * 8 + cA;
                ah[mt][0] = tf32_of(As[r * A_STR + c]);
                ah[mt][1] = tf32_of(As[(r + 8) * A_STR + c]);
                ah[mt][2] = tf32_of(As[r * A_STR + c + 4]);
                ah[mt][3] = tf32_of(As[(r + 8) * A_STR + c + 4]);
            }
            uint32_t bh[4][2];
#pragma unroll
            for (int nt = 0; nt < 4; ++nt) {
                const int n = wn + nt * 8 + rA;
                const int k = ks * 8 + cA;
                bh[nt][0] = tf32_of(Bs[k * B_STR + n]);
                bh[nt][1] = tf32_of(Bs[(k + 4) * B_STR + n]);
            }
#pragma unroll
            for (int mt = 0; mt < 2; ++mt)
#pragma unroll
                for (int nt = 0; nt < 4; ++nt)
                    mma8(acc[mt][nt], ah[mt], bh[nt]);
        }
    }

#pragma unroll
    for (int mt = 0; mt < 2; ++mt) {
        const int r0 = m0 + wm + mt * 16 + rA;
#pragma unroll
        for (int nt = 0; nt < 4; ++nt) {
            const int cg = s0 + wn + nt * 8 + cA * 2;
            const float be0 = b_enc[cg], be1 = b_enc[cg + 1];
            float2 v0 = { acc[mt][nt][0] + be0, acc[mt][nt][1] + be1 };
            float2 v1 = { acc[mt][nt][2] + be0, acc[mt][nt][3] + be1 };
            *(float2*)(g_pre + (size_t)r0 * DSAE + cg)       = v0;
            *(float2*)(g_pre + (size_t)(r0 + 8) * DSAE + cg) = v1;
        }
    }
}

// =====================================================================
// Kernel 2: TopK with exact-boundary refinement (fp64 recompute of
// window candidates). Deterministic.
// =====================================================================
__global__ __launch_bounds__(256) void topk_kernel(
    const float* __restrict__ x,
    const float* __restrict__ W,
    const float* __restrict__ b_enc,
    float* __restrict__ z_out)
{
    const int row = blockIdx.x;           // t-major
    const int tid = threadIdx.x;
    const int t = row >> 3, b = row & 7;
    const int zrow = b * Tn + t;

    __shared__ unsigned us[DSAE];
    __shared__ unsigned hist[256];
    __shared__ unsigned s_prefix;
    __shared__ int      s_k;
    __shared__ int      cnts[256];
    __shared__ int      win_idx[WCAP];
    __shared__ float    win_f[WCAP];
    __shared__ double   win_e[WCAP];
    __shared__ unsigned char win_sel[WCAP];
    __shared__ double   redd[256];
    __shared__ int      s_nhi, s_w;

    const float* rp = g_pre + (size_t)row * DSAE;

    for (int j = tid; j < DSAE; j += 256) {
        unsigned u = __float_as_uint(rp[j]);
        us[j] = (u & 0x80000000u) ? ~u : (u | 0x80000000u);
    }
    if (tid == 0) { s_prefix = 0u; s_k = TOPK; }
    __syncthreads();

    for (int p = 24; p >= 0; p -= 8) {
        hist[tid] = 0u;
        __syncthreads();
        const unsigned pref = s_prefix;
        const int shift_hi = p + 8;
        for (int j = tid; j < DSAE; j += 256) {
            const unsigned u = us[j];
            const bool match = (shift_hi >= 32) || (((u ^ pref) >> shift_hi) == 0u);
            if (match) atomicAdd(&hist[(u >> p) & 255u], 1u);
        }
        __syncthreads();
        if (tid == 0) {
            int k = s_k;
            unsigned c = 0;
            for (int bin = 255; bin >= 0; --bin) {
                const unsigned h = hist[bin];
                if (c + h >= (unsigned)k) {
                    s_prefix = pref | ((unsigned)bin << p);
                    s_k = k - (int)c;
                    break;
                }
                c += h;
            }
        }
        __syncthreads();
    }

    const unsigned T = s_prefix;
    const unsigned iv = (T & 0x80000000u) ? (T & 0x7FFFFFFFu) : ~T;
    const float v64f = __uint_as_float(iv);
    const float dlt = 2e-2f + 2e-3f * fabsf(v64f);
    const float hiT = v64f + dlt, loT = v64f - dlt;

    int chi = 0, cwin = 0;
    for (int q = 0; q < DSAE / 256; ++q) {
        const int j = tid + q * 256;
        const unsigned u = us[j];
        const unsigned ui = (u & 0x80000000u) ? (u & 0x7FFFFFFFu) : ~u;
        const float f = __uint_as_float(ui);
        if (f > hiT) { if (f > 0.f) chi++; }
        else if (f >= loT) cwin++;
    }
    cnts[tid] = chi;
    hist[tid] = (unsigned)cwin;
    __syncthreads();
    if (tid == 0) {
        int run = 0;
        for (int i = 0; i < 256; ++i) { const int c = cnts[i]; cnts[i] = run; run += c; }
        s_nhi = run;
        int wr = 0;
        for (int i = 0; i < 256; ++i) { const int c = (int)hist[i]; hist[i] = (unsigned)wr; wr += c; }
        s_w = wr;
    }
    __syncthreads();

    int pos  = cnts[tid];
    int wpos = (int)hist[tid];
    for (int q = 0; q < DSAE / 256; ++q) {
        const int j = tid + q * 256;
        const unsigned u = us[j];
        const unsigned ui = (u & 0x80000000u) ? (u & 0x7FFFFFFFu) : ~u;
        const float f = __uint_as_float(ui);
        if (f > hiT) {
            if (f > 0.f) {
                if (pos < TOPK) {
                    g_idx[row * TOPK + pos] = j;
                    g_val[row * TOPK + pos] = f;
                }
                z_out[(size_t)zrow * DSAE + j] = f;
                pos++;
            }
        } else if (f >= loT) {
            if (wpos < WCAP) { win_idx[wpos] = j; win_f[wpos] = f; }
            wpos++;
        }
    }
    __syncthreads();

    const int nhi  = s_nhi;
    const int w    = (s_w < WCAP) ? s_w : WCAP;
    int need = TOPK - nhi;
    if (need < 0) need = 0;

    if (w > need) {
        const int kmax = (t + 1) * DIN;
        for (int c = 0; c < w; ++c) {
            const int s = win_idx[c];
            double p0 = 0.0, p1 = 0.0, p2 = 0.0, p3 = 0.0;
            int k = tid;
            for (; k + 768 < kmax; k += 1024) {
                {
                    const int off = k / DIN, d = k - off * DIN;
                    p0 += (double)x[(b * Tn + (t - off)) * DIN + d] * (double)W[(size_t)k * DSAE + s];
                }
                {
                    const int kk = k + 256;
                    const int off = kk / DIN, d = kk - off * DIN;
                    p1 += (double)x[(b * Tn + (t - off)) * DIN + d] * (double)W[(size_t)kk * DSAE + s];
                }
                {
                    const int kk = k + 512;
                    const int off = kk / DIN, d = kk - off * DIN;
                    p2 += (double)x[(b * Tn + (t - off)) * DIN + d] * (double)W[(size_t)kk * DSAE + s];
                }
                {
                    const int kk = k + 768;
                    const int off = kk / DIN, d = kk - off * DIN;
                    p3 += (double)x[(b * Tn + (t - off)) * DIN + d] * (double)W[(size_t)kk * DSAE + s];
                }
            }
            for (; k < kmax; k += 256) {
                const int off = k / DIN, d = k - off * DIN;
                p0 += (double)x[(b * Tn + (t - off)) * DIN + d] * (double)W[(size_t)k * DSAE + s];
            }
            redd[tid] = (p0 + p1) + (p2 + p3);
            __syncthreads();
#pragma unroll
            for (int st = 128; st > 0; st >>= 1) {
                if (tid < st) redd[tid] += redd[tid + st];
                __syncthreads();
            }
            if (tid == 0) win_e[c] = redd[0] + (double)b_enc[s];
            __syncthreads();
        }
        if (tid == 0) {
            for (int c = 0; c < w; ++c) win_sel[c] = 0;
            for (int r = 0; r < need; ++r) {
                int best = -1; double bv = -1e300;
                for (int c = 0; c < w; ++c)
                    if (!win_sel[c] && win_e[c] > bv) { bv = win_e[c]; best = c; }
                if (best >= 0) win_sel[best] = 1;
            }
        }
    } else {
        if (tid == 0) for (int c = 0; c < w; ++c) win_sel[c] = 1;
    }
    __syncthreads();

    if (tid == 0) {
        int p = (nhi > TOPK) ? TOPK : nhi;
        for (int c = 0; c < w; ++c) {
            if (win_sel[c]) {
                const float f = win_f[c];
                if (f > 0.f) {
                    if (p < TOPK) {
                        g_idx[row * TOPK + p] = win_idx[c];
                        g_val[row * TOPK + p] = f;
                    }
                    z_out[(size_t)zrow * DSAE + win_idx[c]] = f;
                    p++;
                }
            }
        }
        g_cnt[row] = (p > TOPK) ? TOPK : p;
    }
}

// =====================================================================
// Kernel 3: sparse decode + fused loss (deterministic integer atomics).
// =====================================================================
__global__ __launch_bounds__(256) void decode_kernel(
    const float* __restrict__ x,
    const float* __restrict__ W_dec,
    const float* __restrict__ b_dec,
    float* __restrict__ xhat,
    float* __restrict__ loss_out)
{
    const int row = blockIdx.x;                   // t-major
    const int bt  = (row & 7) * Tn + (row >> 3);  // (b,t)-major
    const int tid = threadIdx.x;

    __shared__ float sval[TOPK];
    __shared__ int   sidx[TOPK];
    __shared__ float red[256];

    const int cnt = g_cnt[row];
    if (tid < TOPK) {
        sval[tid] = (tid < cnt) ? g_val[row * TOPK + tid] : 0.f;
        sidx[tid] = (tid < cnt) ? g_idx[row * TOPK + tid] : 0;
    }
    __syncthreads();

    float a0 = b_dec[tid];
    float a1 = b_dec[tid + 256];
    float a2 = b_dec[tid + 512];

    for (int kk = 0; kk < cnt; ++kk) {
        const float v = sval[kk];
        const float* wd = W_dec + (size_t)sidx[kk] * DIN;
        a0 = fmaf(v, wd[tid],       a0);
        a1 = fmaf(v, wd[tid + 256], a1);
        a2 = fmaf(v, wd[tid + 512], a2);
    }

    const size_t bbase = (size_t)bt * DIN;
    xhat[bbase + tid]       = a0;
    xhat[bbase + tid + 256] = a1;
    xhat[bbase + tid + 512] = a2;

    const float d0 = a0 - x[bbase + tid];
    const float d1 = a1 - x[bbase + tid + 256];
    const float d2 = a2 - x[bbase + tid + 512];
    red[tid] = d0 * d0 + d1 * d1 + d2 * d2;
    __syncthreads();
#pragma unroll
    for (int st = 128; st > 0; st >>= 1) {
        if (tid < st) red[tid] += red[tid + st];
        __syncthreads();
    }
    if (tid == 0) {
        // fixed-point S=2^20: integer adds are associative -> deterministic
        const unsigned long long q =
            (unsigned long long)__double2ll_rn((double)red[0] * 1048576.0);
        atomicAdd(&g_loss_acc, q);
        __threadfence();
        const int n = atomicAdd(&g_done_ctr, 1);
        if (n == MROWS - 1) {
            loss_out[0] = (float)((double)g_loss_acc *
                                  (1.0 / 1048576.0) * (1.0 / MROWS));
        }
    }
}

// =====================================================================
extern "C" void kernel_launch(void* const* d_in, const int* in_sizes, int n_in,
                              void* d_out, int out_size)
{
    const float* x      = (const float*)d_in[0];
    const float* W_enc  = (const float*)d_in[1];
    const float* W_dec  = (const float*)d_in[2];
    const float* b_enc  = (const float*)d_in[3];
    const float* b_dec  = (const float*)d_in[4];

    float* out  = (float*)d_out;
    float* loss = out;
    float* xhat = out + 1;
    float* z    = out + 1 + XHAT_ELEMS;

    cudaFuncSetAttribute(enc_mma_kernel,
                         cudaFuncAttributeMaxDynamicSharedMemorySize,
                         STAGES * STAGE_BYTES);

    // Launch order tuned so enc_mma is the 6th device launch overall
    // (harness 0xAA poison = #1): memset, 3 dummies, enc <- ncu -s 5 -c 1.
    cudaMemsetAsync(z, 0, Z_ELEMS * sizeof(float));
    dummy_kernel<<<1, 32>>>();
    dummy_kernel<<<1, 32>>>();
    dummy_kernel<<<1, 32>>>();

    dim3 grid(4, DSAE / NTW);
    enc_mma_kernel<<<grid, 128, STAGES * STAGE_BYTES>>>(x, W_enc, b_enc);
    topk_kernel<<<MROWS, 256>>>(x, W_enc, b_enc, z);
    decode_kernel<<<MROWS, 256>>>(x, W_dec, b_dec, xhat, loss);
}

// round 8
// speedup vs baseline: 1.1313x; 1.1313x over previous
#include <cuda_runtime.h>
#include <cstdint>

// Problem constants
#define Bn    8
#define Tn    32
#define DIN   768
#define DSAE  8192
#define TOPK  64
#define MROWS 256
#define XHAT_ELEMS (MROWS * DIN)
#define Z_ELEMS    ((size_t)MROWS * DSAE)
#define WCAP  48

// GEMM tiling
#define MTW   64
#define NTW   64
#define KB    32
#define STAGES 4
#define KB_PER_CHUNK 96          // equal work per block
#define NCHUNK 20                // sum over g of 2*(g+1)
#define A_STR 36
#define B_STR 72
#define A_F   (MTW * A_STR)
#define B_F   (KB * B_STR)
#define STAGE_F (A_F + B_F)
#define A_BYTES (A_F * 4)
#define STAGE_BYTES (STAGE_F * 4)

// ---------------- scratch (no allocations allowed) ----------------
__device__ float g_pre[(size_t)MROWS * DSAE];                 // 8 MB, t-major
__device__ float g_part[(size_t)NCHUNK * 128 * 4096];         // 40 MB split-K partials
__device__ int   g_idx[MROWS * TOPK];
__device__ float g_val[MROWS * TOPK];
__device__ int   g_cnt[MROWS];
__device__ unsigned long long g_loss_acc;
__device__ int   g_done_ctr;

// ================= helpers (plain sm_80+ PTX only) =================
__device__ __forceinline__ uint32_t smem_u32(const void* p) {
    uint32_t a;
    asm("{ .reg .u64 t; cvta.to.shared.u64 t, %1; cvt.u32.u64 %0, t; }" : "=r"(a) : "l"(p));
    return a;
}
__device__ __forceinline__ void cp16(uint32_t dst, const void* src, int srcsize) {
    asm volatile("cp.async.cg.shared.global [%0], [%1], 16, %2;"
                 :: "r"(dst), "l"(src), "r"(srcsize) : "memory");
}
#define CP_COMMIT() asm volatile("cp.async.commit_group;" ::: "memory")
#define CP_WAIT2()  asm volatile("cp.async.wait_group 2;" ::: "memory")

__device__ __forceinline__ void mma8(float* c, const uint32_t* a, const uint32_t* b) {
    asm volatile(
        "mma.sync.aligned.m16n8k8.row.col.f32.tf32.tf32.f32 "
        "{%0,%1,%2,%3}, {%4,%5,%6,%7}, {%8,%9}, {%0,%1,%2,%3};"
        : "+f"(c[0]), "+f"(c[1]), "+f"(c[2]), "+f"(c[3])
        : "r"(a[0]), "r"(a[1]), "r"(a[2]), "r"(a[3]), "r"(b[0]), "r"(b[1]));
}

// =====================================================================
// Stage copy: A 64m x 32k causal im2col (cp.async zero-fill); B 32k x 64n.
// =====================================================================
__device__ __forceinline__ void copy_stage(
    uint32_t sbase, int kb, int m0,
    const float* __restrict__ x, const float* __restrict__ W, int s0, int tid)
{
#pragma unroll
    for (int q = 0; q < 4; ++q) {
        const int ch  = tid + q * 128;
        const int row = ch >> 3, c4 = ch & 7;
        const int kg  = kb * KB + c4 * 4;
        const int off = kg / DIN;
        const int d   = kg - off * DIN;
        const int mrow = m0 + row;
        const int t = mrow >> 3, b = mrow & 7;
        const bool ok = (off <= t);
        const int  tt = ok ? (t - off) : 0;
        const float* src = x + ((b * Tn + tt) * DIN + d);
        cp16(sbase + row * (A_STR * 4) + c4 * 16, src, ok ? 16 : 0);
    }
#pragma unroll
    for (int q = 0; q < 4; ++q) {
        const int ch = tid + q * 128;
        const int kr = ch >> 4, c = ch & 15;
        const float* src = W + (size_t)(kb * KB + kr) * DSAE + s0 + c * 4;
        cp16(sbase + A_BYTES + kr * (B_STR * 4) + c * 16, src, 16);
    }
}

// =====================================================================
// Dummy kernel (ncu alignment so enc lands on profiled launch #6) + reset.
// =====================================================================
__global__ void dummy_kernel() {
    if (threadIdx.x == 0 && blockIdx.x == 0) { g_loss_acc = 0ULL; g_done_ctr = 0; }
}

// =====================================================================
// Kernel 1: encoder GEMM, raw-fp32-as-tf32 mma.sync, SPLIT-K balanced.
// Grid (20, 128): x = chunk c -> (m-group g, k-slice), y = n-tile.
// Every block does exactly 96 kblocks -> flat occupancy, no causal tail.
// Partials (no bias) -> g_part[(c*128+ny)*4096].
// =====================================================================
__global__ __launch_bounds__(128, 3) void enc_mma_kernel(
    const float* __restrict__ x,
    const float* __restrict__ W)
{
    extern __shared__ float sm[];
    const uint32_t smb = smem_u32(sm);
    const int tid = threadIdx.x, lane = tid & 31, wid = tid >> 5;
    const int c  = blockIdx.x;
    const int ny = blockIdx.y;
    const int s0 = ny * NTW;
    // chunk -> (g, slice): starts {0,2,6,12}
    const int g  = (c < 2) ? 0 : (c < 6) ? 1 : (c < 12) ? 2 : 3;
    const int kb0 = (c - g * (g + 1)) * KB_PER_CHUNK;
    const int m0  = g * MTW;
    const int wm  = (wid & 1) * 32, wn = (wid >> 1) * 32;

    float acc[2][4][4];
#pragma unroll
    for (int a = 0; a < 2; ++a)
#pragma unroll
        for (int b = 0; b < 4; ++b)
#pragma unroll
            for (int cc = 0; cc < 4; ++cc) acc[a][b][cc] = 0.f;

#pragma unroll
    for (int p = 0; p < STAGES - 1; ++p) {
        copy_stage(smb + p * STAGE_BYTES, kb0 + p, m0, x, W, s0, tid);
        CP_COMMIT();
    }

    const int rA = lane >> 2;
    const int cA = lane & 3;

    for (int i = 0; i < KB_PER_CHUNK; ++i) {
        CP_WAIT2();
        __syncthreads();

        const int nx = i + STAGES - 1;
        if (nx < KB_PER_CHUNK)
            copy_stage(smb + (nx & 3) * STAGE_BYTES, kb0 + nx, m0, x, W, s0, tid);
        CP_COMMIT();

        const float* As = sm + (i & 3) * STAGE_F;
        const float* Bs = As + A_F;
        const uint32_t* Au = (const uint32_t*)As;
        const uint32_t* Bu = (const uint32_t*)Bs;

#pragma unroll
        for (int ks = 0; ks < 4; ++ks) {
            uint32_t ah[2][4];
#pragma unroll
            for (int mt = 0; mt < 2; ++mt) {
                const int r = wm + mt * 16 + rA;
                const int cc = ks * 8 + cA;
                ah[mt][0] = Au[r * A_STR + cc];         // raw fp32 bits: HW
                ah[mt][1] = Au[(r + 8) * A_STR + cc];   // truncates to tf32
                ah[mt][2] = Au[r * A_STR + cc + 4];
                ah[mt][3] = Au[(r + 8) * A_STR + cc + 4];
            }
            uint32_t bh[4][2];
#pragma unroll
            for (int nt = 0; nt < 4; ++nt) {
                const int n = wn + nt * 8 + rA;
                const int k = ks * 8 + cA;
                bh[nt][0] = Bu[k * B_STR + n];
                bh[nt][1] = Bu[(k + 4) * B_STR + n];
            }
#pragma unroll
            for (int mt = 0; mt < 2; ++mt)
#pragma unroll
                for (int nt = 0; nt < 4; ++nt)
                    mma8(acc[mt][nt], ah[mt], bh[nt]);
        }
    }

    // ---- epilogue: raw partial tile -> g_part ----
    float* pt = g_part + (size_t)(c * 128 + ny) * 4096;
#pragma unroll
    for (int mt = 0; mt < 2; ++mt) {
        const int r0 = wm + mt * 16 + rA;
#pragma unroll
        for (int nt = 0; nt < 4; ++nt) {
            const int cl = wn + nt * 8 + cA * 2;
            float2 v0 = { acc[mt][nt][0], acc[mt][nt][1] };
            float2 v1 = { acc[mt][nt][2], acc[mt][nt][3] };
            *(float2*)(pt + r0 * 64 + cl)       = v0;
            *(float2*)(pt + (r0 + 8) * 64 + cl) = v1;
        }
    }
}

// =====================================================================
// Kernel 1b: deterministic split-K reduction + bias -> g_pre.
// Grid 512: bx = g*128 + ny. 256 threads over the 64x64 tile.
// =====================================================================
__global__ __launch_bounds__(256) void reduce_kernel(const float* __restrict__ b_enc)
{
    const int bx = blockIdx.x;
    const int g  = bx >> 7, ny = bx & 127;
    const int nch = 2 * (g + 1);
    const int cstart = g * (g + 1);
    const int tid = threadIdx.x;

    for (int idx = tid; idx < 4096; idx += 256) {
        const int row = idx >> 6, col = idx & 63;
        float s = b_enc[ny * 64 + col];
        const float* p = g_part + (size_t)(cstart * 128 + ny) * 4096 + idx;
        for (int cc = 0; cc < nch; ++cc)
            s += p[(size_t)cc * 128 * 4096];
        g_pre[(size_t)(g * 64 + row) * DSAE + ny * 64 + col] = s;
    }
}

// =====================================================================
// Kernel 2: TopK with exact-boundary refinement (fp64 recompute).
// =====================================================================
__global__ __launch_bounds__(256) void topk_kernel(
    const float* __restrict__ x,
    const float* __restrict__ W,
    const float* __restrict__ b_enc,
    float* __restrict__ z_out)
{
    const int row = blockIdx.x;           // t-major
    const int tid = threadIdx.x;
    const int t = row >> 3, b = row & 7;
    const int zrow = b * Tn + t;

    __shared__ unsigned us[DSAE];
    __shared__ unsigned hist[256];
    __shared__ unsigned s_prefix;
    __shared__ int      s_k;
    __shared__ int      cnts[256];
    __shared__ int      win_idx[WCAP];
    __shared__ float    win_f[WCAP];
    __shared__ double   win_e[WCAP];
    __shared__ unsigned char win_sel[WCAP];
    __shared__ double   redd[256];
    __shared__ int      s_nhi, s_w;

    const float* rp = g_pre + (size_t)row * DSAE;

    for (int j = tid; j < DSAE; j += 256) {
        unsigned u = __float_as_uint(rp[j]);
        us[j] = (u & 0x80000000u) ? ~u : (u | 0x80000000u);
    }
    if (tid == 0) { s_prefix = 0u; s_k = TOPK; }
    __syncthreads();

    for (int p = 24; p >= 0; p -= 8) {
        hist[tid] = 0u;
        __syncthreads();
        const unsigned pref = s_prefix;
        const int shift_hi = p + 8;
        for (int j = tid; j < DSAE; j += 256) {
            const unsigned u = us[j];
            const bool match = (shift_hi >= 32) || (((u ^ pref) >> shift_hi) == 0u);
            if (match) atomicAdd(&hist[(u >> p) & 255u], 1u);
        }
        __syncthreads();
        if (tid == 0) {
            int k = s_k;
            unsigned c = 0;
            for (int bin = 255; bin >= 0; --bin) {
                const unsigned h = hist[bin];
                if (c + h >= (unsigned)k) {
                    s_prefix = pref | ((unsigned)bin << p);
                    s_k = k - (int)c;
                    break;
                }
                c += h;
            }
        }
        __syncthreads();
    }

    const unsigned T = s_prefix;
    const unsigned iv = (T & 0x80000000u) ? (T & 0x7FFFFFFFu) : ~T;
    const float v64f = __uint_as_float(iv);
    const float dlt = 3e-2f + 3e-3f * fabsf(v64f);   // ~10 sigma of truncation error
    const float hiT = v64f + dlt, loT = v64f - dlt;

    int chi = 0, cwin = 0;
    for (int q = 0; q < DSAE / 256; ++q) {
        const int j = tid + q * 256;
        const unsigned u = us[j];
        const unsigned ui = (u & 0x80000000u) ? (u & 0x7FFFFFFFu) : ~u;
        const float f = __uint_as_float(ui);
        if (f > hiT) { if (f > 0.f) chi++; }
        else if (f >= loT) cwin++;
    }
    cnts[tid] = chi;
    hist[tid] = (unsigned)cwin;
    __syncthreads();
    if (tid == 0) {
        int run = 0;
        for (int i = 0; i < 256; ++i) { const int c = cnts[i]; cnts[i] = run; run += c; }
        s_nhi = run;
        int wr = 0;
        for (int i = 0; i < 256; ++i) { const int c = (int)hist[i]; hist[i] = (unsigned)wr; wr += c; }
        s_w = wr;
    }
    __syncthreads();

    int pos  = cnts[tid];
    int wpos = (int)hist[tid];
    for (int q = 0; q < DSAE / 256; ++q) {
        const int j = tid + q * 256;
        const unsigned u = us[j];
        const unsigned ui = (u & 0x80000000u) ? (u & 0x7FFFFFFFu) : ~u;
        const float f = __uint_as_float(ui);
        if (f > hiT) {
            if (f > 0.f) {
                if (pos < TOPK) {
                    g_idx[row * TOPK + pos] = j;
                    g_val[row * TOPK + pos] = f;
                }
                z_out[(size_t)zrow * DSAE + j] = f;
                pos++;
            }
        } else if (f >= loT) {
            if (wpos < WCAP) { win_idx[wpos] = j; win_f[wpos] = f; }
            wpos++;
        }
    }
    __syncthreads();

    const int nhi  = s_nhi;
    const int w    = (s_w < WCAP) ? s_w : WCAP;
    int need = TOPK - nhi;
    if (need < 0) need = 0;

    if (w > need) {
        const int kmax = (t + 1) * DIN;
        for (int c = 0; c < w; ++c) {
            const int s = win_idx[c];
            double p0 = 0.0, p1 = 0.0, p2 = 0.0, p3 = 0.0;
            int k = tid;
            for (; k + 768 < kmax; k += 1024) {
                {
                    const int off = k / DIN, d = k - off * DIN;
                    p0 += (double)x[(b * Tn + (t - off)) * DIN + d] * (double)W[(size_t)k * DSAE + s];
                }
                {
                    const int kk = k + 256;
                    const int off = kk / DIN, d = kk - off * DIN;
                    p1 += (double)x[(b * Tn + (t - off)) * DIN + d] * (double)W[(size_t)kk * DSAE + s];
                }
                {
                    const int kk = k + 512;
                    const int off = kk / DIN, d = kk - off * DIN;
                    p2 += (double)x[(b * Tn + (t - off)) * DIN + d] * (double)W[(size_t)kk * DSAE + s];
                }
                {
                    const int kk = k + 768;
                    const int off = kk / DIN, d = kk - off * DIN;
                    p3 += (double)x[(b * Tn + (t - off)) * DIN + d] * (double)W[(size_t)kk * DSAE + s];
                }
            }
            for (; k < kmax; k += 256) {
                const int off = k / DIN, d = k - off * DIN;
                p0 += (double)x[(b * Tn + (t - off)) * DIN + d] * (double)W[(size_t)k * DSAE + s];
            }
            redd[tid] = (p0 + p1) + (p2 + p3);
            __syncthreads();
#pragma unroll
            for (int st = 128; st > 0; st >>= 1) {
                if (tid < st) redd[tid] += redd[tid + st];
                __syncthreads();
            }
            if (tid == 0) win_e[c] = redd[0] + (double)b_enc[s];
            __syncthreads();
        }
        if (tid == 0) {
            for (int c = 0; c < w; ++c) win_sel[c] = 0;
            for (int r = 0; r < need; ++r) {
                int best = -1; double bv = -1e300;
                for (int c = 0; c < w; ++c)
                    if (!win_sel[c] && win_e[c] > bv) { bv = win_e[c]; best = c; }
                if (best >= 0) win_sel[best] = 1;
            }
        }
    } else {
        if (tid == 0) for (int c = 0; c < w; ++c) win_sel[c] = 1;
    }
    __syncthreads();

    if (tid == 0) {
        int p = (nhi > TOPK) ? TOPK : nhi;
        for (int c = 0; c < w; ++c) {
            if (win_sel[c]) {
                const float f = win_f[c];
                if (f > 0.f) {
                    if (p < TOPK) {
                        g_idx[row * TOPK + p] = win_idx[c];
                        g_val[row * TOPK + p] = f;
                    }
                    z_out[(size_t)zrow * DSAE + win_idx[c]] = f;
                    p++;
                }
            }
        }
        g_cnt[row] = (p > TOPK) ? TOPK : p;
    }
}

// =====================================================================
// Kernel 3: sparse decode + fused loss (deterministic integer atomics).
// =====================================================================
__global__ __launch_bounds__(256) void decode_kernel(
    const float* __restrict__ x,
    const float* __restrict__ W_dec,
    const float* __restrict__ b_dec,
    float* __restrict__ xhat,
    float* __restrict__ loss_out)
{
    const int row = blockIdx.x;                   // t-major
    const int bt  = (row & 7) * Tn + (row >> 3);  // (b,t)-major
    const int tid = threadIdx.x;

    __shared__ float sval[TOPK];
    __shared__ int   sidx[TOPK];
    __shared__ float red[256];

    const int cnt = g_cnt[row];
    if (tid < TOPK) {
        sval[tid] = (tid < cnt) ? g_val[row * TOPK + tid] : 0.f;
        sidx[tid] = (tid < cnt) ? g_idx[row * TOPK + tid] : 0;
    }
    __syncthreads();

    float a0 = b_dec[tid];
    float a1 = b_dec[tid + 256];
    float a2 = b_dec[tid + 512];

    for (int kk = 0; kk < cnt; ++kk) {
        const float v = sval[kk];
        const float* wd = W_dec + (size_t)sidx[kk] * DIN;
        a0 = fmaf(v, wd[tid],       a0);
        a1 = fmaf(v, wd[tid + 256], a1);
        a2 = fmaf(v, wd[tid + 512], a2);
    }

    const size_t bbase = (size_t)bt * DIN;
    xhat[bbase + tid]       = a0;
    xhat[bbase + tid + 256] = a1;
    xhat[bbase + tid + 512] = a2;

    const float d0 = a0 - x[bbase + tid];
    const float d1 = a1 - x[bbase + tid + 256];
    const float d2 = a2 - x[bbase + tid + 512];
    red[tid] = d0 * d0 + d1 * d1 + d2 * d2;
    __syncthreads();
#pragma unroll
    for (int st = 128; st > 0; st >>= 1) {
        if (tid < st) red[tid] += red[tid + st];
        __syncthreads();
    }
    if (tid == 0) {
        const unsigned long long q =
            (unsigned long long)__double2ll_rn((double)red[0] * 1048576.0);
        atomicAdd(&g_loss_acc, q);
        __threadfence();
        const int n = atomicAdd(&g_done_ctr, 1);
        if (n == MROWS - 1) {
            loss_out[0] = (float)((double)g_loss_acc *
                                  (1.0 / 1048576.0) * (1.0 / MROWS));
        }
    }
}

// =====================================================================
extern "C" void kernel_launch(void* const* d_in, const int* in_sizes, int n_in,
                              void* d_out, int out_size)
{
    const float* x      = (const float*)d_in[0];
    const float* W_enc  = (const float*)d_in[1];
    const float* W_dec  = (const float*)d_in[2];
    const float* b_enc  = (const float*)d_in[3];
    const float* b_dec  = (const float*)d_in[4];

    float* out  = (float*)d_out;
    float* loss = out;
    float* xhat = out + 1;
    float* z    = out + 1 + XHAT_ELEMS;

    cudaFuncSetAttribute(enc_mma_kernel,
                         cudaFuncAttributeMaxDynamicSharedMemorySize,
                         STAGES * STAGE_BYTES);

    // Launch order: harness poison(#1), memset z(#2), dummies(#3-5),
    // enc(#6 <- ncu -s 5 -c 1 profiles this).
    cudaMemsetAsync(z, 0, Z_ELEMS * sizeof(float));
    dummy_kernel<<<1, 32>>>();
    dummy_kernel<<<1, 32>>>();
    dummy_kernel<<<1, 32>>>();

    dim3 grid(NCHUNK, DSAE / NTW);
    enc_mma_kernel<<<grid, 128, STAGES * STAGE_BYTES>>>(x, W_enc);
    reduce_kernel<<<512, 256>>>(b_enc);
    topk_kernel<<<MROWS, 256>>>(x, W_enc, b_enc, z);
    decode_kernel<<<MROWS, 256>>>(x, W_dec, b_dec, xhat, loss);
}

// round 9
// speedup vs baseline: 1.5493x; 1.3696x over previous
#include <cuda_runtime.h>
#include <cstdint>

// Problem constants
#define Bn    8
#define Tn    32
#define DIN   768
#define DSAE  8192
#define TOPK  64
#define MROWS 256
#define XHAT_ELEMS (MROWS * DIN)
#define Z_ELEMS    ((size_t)MROWS * DSAE)
#define WCAP  48

// GEMM tiling
#define MTW   64
#define NTW   64
#define KB    32
#define STAGES 4
#define KB_PER_CHUNK 96          // equal work per block
#define NCHUNK 20                // sum over g of 2*(g+1)
#define A_STR 36
#define B_STR 72
#define A_F   (MTW * A_STR)
#define B_F   (KB * B_STR)
#define STAGE_F (A_F + B_F)
#define A_BYTES (A_F * 4)
#define STAGE_BYTES (STAGE_F * 4)

// ---------------- scratch (no allocations allowed) ----------------
__device__ float g_pre[(size_t)MROWS * DSAE];                 // 8 MB, t-major
__device__ float g_part[(size_t)NCHUNK * 128 * 4096];         // 40 MB split-K partials
__device__ int   g_idx[MROWS * TOPK];
__device__ float g_val[MROWS * TOPK];
__device__ int   g_cnt[MROWS];
__device__ unsigned long long g_loss_acc;
__device__ int   g_done_ctr;

// ================= helpers (plain sm_80+ PTX only) =================
__device__ __forceinline__ uint32_t smem_u32(const void* p) {
    uint32_t a;
    asm("{ .reg .u64 t; cvta.to.shared.u64 t, %1; cvt.u32.u64 %0, t; }" : "=r"(a) : "l"(p));
    return a;
}
__device__ __forceinline__ void cp16(uint32_t dst, const void* src, int srcsize) {
    asm volatile("cp.async.cg.shared.global [%0], [%1], 16, %2;"
                 :: "r"(dst), "l"(src), "r"(srcsize) : "memory");
}
#define CP_COMMIT() asm volatile("cp.async.commit_group;" ::: "memory")
#define CP_WAIT2()  asm volatile("cp.async.wait_group 2;" ::: "memory")

// tf32 hi/lo split: hi = rna(tf32); lo = remainder (raw bits, truncated by HW)
__device__ __forceinline__ void split2(float v, uint32_t& h, uint32_t& l) {
    asm("cvt.rna.tf32.f32 %0, %1;" : "=r"(h) : "f"(v));
    l = __float_as_uint(v - __uint_as_float(h));
}

__device__ __forceinline__ void mma8(float* c, const uint32_t* a, const uint32_t* b) {
    asm volatile(
        "mma.sync.aligned.m16n8k8.row.col.f32.tf32.tf32.f32 "
        "{%0,%1,%2,%3}, {%4,%5,%6,%7}, {%8,%9}, {%0,%1,%2,%3};"
        : "+f"(c[0]), "+f"(c[1]), "+f"(c[2]), "+f"(c[3])
        : "r"(a[0]), "r"(a[1]), "r"(a[2]), "r"(a[3]), "r"(b[0]), "r"(b[1]));
}

// =====================================================================
// Stage copy: A 64m x 32k causal im2col (cp.async zero-fill); B 32k x 64n.
// =====================================================================
__device__ __forceinline__ void copy_stage(
    uint32_t sbase, int kb, int m0,
    const float* __restrict__ x, const float* __restrict__ W, int s0, int tid)
{
#pragma unroll
    for (int q = 0; q < 4; ++q) {
        const int ch  = tid + q * 128;
        const int row = ch >> 3, c4 = ch & 7;
        const int kg  = kb * KB + c4 * 4;
        const int off = kg / DIN;
        const int d   = kg - off * DIN;
        const int mrow = m0 + row;
        const int t = mrow >> 3, b = mrow & 7;
        const bool ok = (off <= t);
        const int  tt = ok ? (t - off) : 0;
        const float* src = x + ((b * Tn + tt) * DIN + d);
        cp16(sbase + row * (A_STR * 4) + c4 * 16, src, ok ? 16 : 0);
    }
#pragma unroll
    for (int q = 0; q < 4; ++q) {
        const int ch = tid + q * 128;
        const int kr = ch >> 4, c = ch & 15;
        const float* src = W + (size_t)(kb * KB + kr) * DSAE + s0 + c * 4;
        cp16(sbase + A_BYTES + kr * (B_STR * 4) + c * 16, src, 16);
    }
}

// =====================================================================
// Dummy kernel (ncu alignment so enc lands on profiled launch #6) + reset.
// =====================================================================
__global__ void dummy_kernel() {
    if (threadIdx.x == 0 && blockIdx.x == 0) { g_loss_acc = 0ULL; g_done_ctr = 0; }
}

// =====================================================================
// Kernel 1: encoder GEMM, 3-term tf32 (hh + hl + lh, rna split), SPLIT-K.
// Grid (20, 128): x = chunk c -> (m-group g, k-slice), y = n-tile.
// Every block does exactly 96 kblocks -> flat occupancy.
// Value precision ~2e-5 abs -> refinement window shrinks 60x.
// =====================================================================
__global__ __launch_bounds__(128, 3) void enc_mma_kernel(
    const float* __restrict__ x,
    const float* __restrict__ W)
{
    extern __shared__ float sm[];
    const uint32_t smb = smem_u32(sm);
    const int tid = threadIdx.x, lane = tid & 31, wid = tid >> 5;
    const int c  = blockIdx.x;
    const int ny = blockIdx.y;
    const int s0 = ny * NTW;
    const int g  = (c < 2) ? 0 : (c < 6) ? 1 : (c < 12) ? 2 : 3;
    const int kb0 = (c - g * (g + 1)) * KB_PER_CHUNK;
    const int m0  = g * MTW;
    const int wm  = (wid & 1) * 32, wn = (wid >> 1) * 32;

    float acc[2][4][4];
#pragma unroll
    for (int a = 0; a < 2; ++a)
#pragma unroll
        for (int b = 0; b < 4; ++b)
#pragma unroll
            for (int cc = 0; cc < 4; ++cc) acc[a][b][cc] = 0.f;

#pragma unroll
    for (int p = 0; p < STAGES - 1; ++p) {
        copy_stage(smb + p * STAGE_BYTES, kb0 + p, m0, x, W, s0, tid);
        CP_COMMIT();
    }

    const int rA = lane >> 2;
    const int cA = lane & 3;

    for (int i = 0; i < KB_PER_CHUNK; ++i) {
        CP_WAIT2();
        __syncthreads();

        const int nx = i + STAGES - 1;
        if (nx < KB_PER_CHUNK)
            copy_stage(smb + (nx & 3) * STAGE_BYTES, kb0 + nx, m0, x, W, s0, tid);
        CP_COMMIT();

        const float* As = sm + (i & 3) * STAGE_F;
        const float* Bs = As + A_F;

#pragma unroll
        for (int ks = 0; ks < 4; ++ks) {
            uint32_t ah[2][4], al[2][4];
#pragma unroll
            for (int mt = 0; mt < 2; ++mt) {
                const int r = wm + mt * 16 + rA;
                const int cc = ks * 8 + cA;
                split2(As[r * A_STR + cc],           ah[mt][0], al[mt][0]);
                split2(As[(r + 8) * A_STR + cc],     ah[mt][1], al[mt][1]);
                split2(As[r * A_STR + cc + 4],       ah[mt][2], al[mt][2]);
                split2(As[(r + 8) * A_STR + cc + 4], ah[mt][3], al[mt][3]);
            }
            uint32_t bh[4][2], bl[4][2];
#pragma unroll
            for (int nt = 0; nt < 4; ++nt) {
                const int n = wn + nt * 8 + rA;
                const int k = ks * 8 + cA;
                split2(Bs[k * B_STR + n],       bh[nt][0], bl[nt][0]);
                split2(Bs[(k + 4) * B_STR + n], bh[nt][1], bl[nt][1]);
            }
#pragma unroll
            for (int mt = 0; mt < 2; ++mt)
#pragma unroll
                for (int nt = 0; nt < 4; ++nt) {
                    float* cc = acc[mt][nt];
                    mma8(cc, ah[mt], bh[nt]);   // hi*hi
                    mma8(cc, ah[mt], bl[nt]);   // hi*lo
                    mma8(cc, al[mt], bh[nt]);   // lo*hi
                }
        }
    }

    // ---- epilogue: raw partial tile -> g_part ----
    float* pt = g_part + (size_t)(c * 128 + ny) * 4096;
#pragma unroll
    for (int mt = 0; mt < 2; ++mt) {
        const int r0 = wm + mt * 16 + rA;
#pragma unroll
        for (int nt = 0; nt < 4; ++nt) {
            const int cl = wn + nt * 8 + cA * 2;
            float2 v0 = { acc[mt][nt][0], acc[mt][nt][1] };
            float2 v1 = { acc[mt][nt][2], acc[mt][nt][3] };
            *(float2*)(pt + r0 * 64 + cl)       = v0;
            *(float2*)(pt + (r0 + 8) * 64 + cl) = v1;
        }
    }
}

// =====================================================================
// Kernel 1b: deterministic split-K reduction + bias -> g_pre.
// =====================================================================
__global__ __launch_bounds__(256) void reduce_kernel(const float* __restrict__ b_enc)
{
    const int bx = blockIdx.x;
    const int g  = bx >> 7, ny = bx & 127;
    const int nch = 2 * (g + 1);
    const int cstart = g * (g + 1);
    const int tid = threadIdx.x;

    for (int idx = tid; idx < 4096; idx += 256) {
        const int row = idx >> 6, col = idx & 63;
        float s = b_enc[ny * 64 + col];
        const float* p = g_part + (size_t)(cstart * 128 + ny) * 4096 + idx;
        for (int cc = 0; cc < nch; ++cc)
            s += p[(size_t)cc * 128 * 4096];
        g_pre[(size_t)(g * 64 + row) * DSAE + ny * 64 + col] = s;
    }
}

// =====================================================================
// Kernel 2: TopK with exact-boundary refinement (tight window, fp64).
// =====================================================================
__global__ __launch_bounds__(256) void topk_kernel(
    const float* __restrict__ x,
    const float* __restrict__ W,
    const float* __restrict__ b_enc,
    float* __restrict__ z_out)
{
    const int row = blockIdx.x;           // t-major
    const int tid = threadIdx.x;
    const int t = row >> 3, b = row & 7;
    const int zrow = b * Tn + t;

    __shared__ unsigned us[DSAE];
    __shared__ unsigned hist[256];
    __shared__ unsigned s_prefix;
    __shared__ int      s_k;
    __shared__ int      cnts[256];
    __shared__ int      win_idx[WCAP];
    __shared__ float    win_f[WCAP];
    __shared__ double   win_e[WCAP];
    __shared__ unsigned char win_sel[WCAP];
    __shared__ double   redd[256];
    __shared__ int      s_nhi, s_w;

    const float* rp = g_pre + (size_t)row * DSAE;

    for (int j = tid; j < DSAE; j += 256) {
        unsigned u = __float_as_uint(rp[j]);
        us[j] = (u & 0x80000000u) ? ~u : (u | 0x80000000u);
    }
    if (tid == 0) { s_prefix = 0u; s_k = TOPK; }
    __syncthreads();

    for (int p = 24; p >= 0; p -= 8) {
        hist[tid] = 0u;
        __syncthreads();
        const unsigned pref = s_prefix;
        const int shift_hi = p + 8;
        for (int j = tid; j < DSAE; j += 256) {
            const unsigned u = us[j];
            const bool match = (shift_hi >= 32) || (((u ^ pref) >> shift_hi) == 0u);
            if (match) atomicAdd(&hist[(u >> p) & 255u], 1u);
        }
        __syncthreads();
        if (tid == 0) {
            int k = s_k;
            unsigned c = 0;
            for (int bin = 255; bin >= 0; --bin) {
                const unsigned h = hist[bin];
                if (c + h >= (unsigned)k) {
                    s_prefix = pref | ((unsigned)bin << p);
                    s_k = k - (int)c;
                    break;
                }
                c += h;
            }
        }
        __syncthreads();
    }

    const unsigned T = s_prefix;
    const unsigned iv = (T & 0x80000000u) ? (T & 0x7FFFFFFFu) : ~T;
    const float v64f = __uint_as_float(iv);
    const float dlt = 5e-4f + 1e-4f * fabsf(v64f);   // >=20 sigma of 3-term error
    const float hiT = v64f + dlt, loT = v64f - dlt;

    int chi = 0, cwin = 0;
    for (int q = 0; q < DSAE / 256; ++q) {
        const int j = tid + q * 256;
        const unsigned u = us[j];
        const unsigned ui = (u & 0x80000000u) ? (u & 0x7FFFFFFFu) : ~u;
        const float f = __uint_as_float(ui);
        if (f > hiT) { if (f > 0.f) chi++; }
        else if (f >= loT) cwin++;
    }
    cnts[tid] = chi;
    hist[tid] = (unsigned)cwin;
    __syncthreads();
    if (tid == 0) {
        int run = 0;
        for (int i = 0; i < 256; ++i) { const int c = cnts[i]; cnts[i] = run; run += c; }
        s_nhi = run;
        int wr = 0;
        for (int i = 0; i < 256; ++i) { const int c = (int)hist[i]; hist[i] = (unsigned)wr; wr += c; }
        s_w = wr;
    }
    __syncthreads();

    int pos  = cnts[tid];
    int wpos = (int)hist[tid];
    for (int q = 0; q < DSAE / 256; ++q) {
        const int j = tid + q * 256;
        const unsigned u = us[j];
        const unsigned ui = (u & 0x80000000u) ? (u & 0x7FFFFFFFu) : ~u;
        const float f = __uint_as_float(ui);
        if (f > hiT) {
            if (f > 0.f) {
                if (pos < TOPK) {
                    g_idx[row * TOPK + pos] = j;
                    g_val[row * TOPK + pos] = f;
                }
                z_out[(size_t)zrow * DSAE + j] = f;
                pos++;
            }
        } else if (f >= loT) {
            if (wpos < WCAP) { win_idx[wpos] = j; win_f[wpos] = f; }
            wpos++;
        }
    }
    __syncthreads();

    const int nhi  = s_nhi;
    const int w    = (s_w < WCAP) ? s_w : WCAP;
    int need = TOPK - nhi;
    if (need < 0) need = 0;

    if (w > need) {
        const int kmax = (t + 1) * DIN;
        for (int c = 0; c < w; ++c) {
            const int s = win_idx[c];
            double p0 = 0.0, p1 = 0.0, p2 = 0.0, p3 = 0.0;
            int k = tid;
            for (; k + 768 < kmax; k += 1024) {
                {
                    const int off = k / DIN, d = k - off * DIN;
                    p0 += (double)x[(b * Tn + (t - off)) * DIN + d] * (double)W[(size_t)k * DSAE + s];
                }
                {
                    const int kk = k + 256;
                    const int off = kk / DIN, d = kk - off * DIN;
                    p1 += (double)x[(b * Tn + (t - off)) * DIN + d] * (double)W[(size_t)kk * DSAE + s];
                }
                {
                    const int kk = k + 512;
                    const int off = kk / DIN, d = kk - off * DIN;
                    p2 += (double)x[(b * Tn + (t - off)) * DIN + d] * (double)W[(size_t)kk * DSAE + s];
                }
                {
                    const int kk = k + 768;
                    const int off = kk / DIN, d = kk - off * DIN;
                    p3 += (double)x[(b * Tn + (t - off)) * DIN + d] * (double)W[(size_t)kk * DSAE + s];
                }
            }
            for (; k < kmax; k += 256) {
                const int off = k / DIN, d = k - off * DIN;
                p0 += (double)x[(b * Tn + (t - off)) * DIN + d] * (double)W[(size_t)k * DSAE + s];
            }
            redd[tid] = (p0 + p1) + (p2 + p3);
            __syncthreads();
#pragma unroll
            for (int st = 128; st > 0; st >>= 1) {
                if (tid < st) redd[tid] += redd[tid + st];
                __syncthreads();
            }
            if (tid == 0) win_e[c] = redd[0] + (double)b_enc[s];
            __syncthreads();
        }
        if (tid == 0) {
            for (int c = 0; c < w; ++c) win_sel[c] = 0;
            for (int r = 0; r < need; ++r) {
                int best = -1; double bv = -1e300;
                for (int c = 0; c < w; ++c)
                    if (!win_sel[c] && win_e[c] > bv) { bv = win_e[c]; best = c; }
                if (best >= 0) win_sel[best] = 1;
            }
        }
    } else {
        if (tid == 0) for (int c = 0; c < w; ++c) win_sel[c] = 1;
    }
    __syncthreads();

    if (tid == 0) {
        int p = (nhi > TOPK) ? TOPK : nhi;
        for (int c = 0; c < w; ++c) {
            if (win_sel[c]) {
                const float f = win_f[c];
                if (f > 0.f) {
                    if (p < TOPK) {
                        g_idx[row * TOPK + p] = win_idx[c];
                        g_val[row * TOPK + p] = f;
                    }
                    z_out[(size_t)zrow * DSAE + win_idx[c]] = f;
                    p++;
                }
            }
        }
        g_cnt[row] = (p > TOPK) ? TOPK : p;
    }
}

// =====================================================================
// Kernel 3: sparse decode + fused loss (deterministic integer atomics).
// =====================================================================
__global__ __launch_bounds__(256) void decode_kernel(
    const float* __restrict__ x,
    const float* __restrict__ W_dec,
    const float* __restrict__ b_dec,
    float* __restrict__ xhat,
    float* __restrict__ loss_out)
{
    const int row = blockIdx.x;                   // t-major
    const int bt  = (row & 7) * Tn + (row >> 3);  // (b,t)-major
    const int tid = threadIdx.x;

    __shared__ float sval[TOPK];
    __shared__ int   sidx[TOPK];
    __shared__ float red[256];

    const int cnt = g_cnt[row];
    if (tid < TOPK) {
        sval[tid] = (tid < cnt) ? g_val[row * TOPK + tid] : 0.f;
        sidx[tid] = (tid < cnt) ? g_idx[row * TOPK + tid] : 0;
    }
    __syncthreads();

    float a0 = b_dec[tid];
    float a1 = b_dec[tid + 256];
    float a2 = b_dec[tid + 512];

    for (int kk = 0; kk < cnt; ++kk) {
        const float v = sval[kk];
        const float* wd = W_dec + (size_t)sidx[kk] * DIN;
        a0 = fmaf(v, wd[tid],       a0);
        a1 = fmaf(v, wd[tid + 256], a1);
        a2 = fmaf(v, wd[tid + 512], a2);
    }

    const size_t bbase = (size_t)bt * DIN;
    xhat[bbase + tid]       = a0;
    xhat[bbase + tid + 256] = a1;
    xhat[bbase + tid + 512] = a2;

    const float d0 = a0 - x[bbase + tid];
    const float d1 = a1 - x[bbase + tid + 256];
    const float d2 = a2 - x[bbase + tid + 512];
    red[tid] = d0 * d0 + d1 * d1 + d2 * d2;
    __syncthreads();
#pragma unroll
    for (int st = 128; st > 0; st >>= 1) {
        if (tid < st) red[tid] += red[tid + st];
        __syncthreads();
    }
    if (tid == 0) {
        const unsigned long long q =
            (unsigned long long)__double2ll_rn((double)red[0] * 1048576.0);
        atomicAdd(&g_loss_acc, q);
        __threadfence();
        const int n = atomicAdd(&g_done_ctr, 1);
        if (n == MROWS - 1) {
            loss_out[0] = (float)((double)g_loss_acc *
                                  (1.0 / 1048576.0) * (1.0 / MROWS));
        }
    }
}

// =====================================================================
extern "C" void kernel_launch(void* const* d_in, const int* in_sizes, int n_in,
                              void* d_out, int out_size)
{
    const float* x      = (const float*)d_in[0];
    const float* W_enc  = (const float*)d_in[1];
    const float* W_dec  = (const float*)d_in[2];
    const float* b_enc  = (const float*)d_in[3];
    const float* b_dec  = (const float*)d_in[4];

    float* out  = (float*)d_out;
    float* loss = out;
    float* xhat = out + 1;
    float* z    = out + 1 + XHAT_ELEMS;

    cudaFuncSetAttribute(enc_mma_kernel,
                         cudaFuncAttributeMaxDynamicSharedMemorySize,
                         STAGES * STAGE_BYTES);

    // Launch order: harness poison(#1), memset z(#2), dummies(#3-5),
    // enc(#6 <- ncu -s 5 -c 1 profiles this).
    cudaMemsetAsync(z, 0, Z_ELEMS * sizeof(float));
    dummy_kernel<<<1, 32>>>();
    dummy_kernel<<<1, 32>>>();
    dummy_kernel<<<1, 32>>>();

    dim3 grid(NCHUNK, DSAE / NTW);
    enc_mma_kernel<<<grid, 128, STAGES * STAGE_BYTES>>>(x, W_enc);
    reduce_kernel<<<512, 256>>>(b_enc);
    topk_kernel<<<MROWS, 256>>>(x, W_enc, b_enc, z);
    decode_kernel<<<MROWS, 256>>>(x, W_dec, b_dec, xhat, loss);
}